// round 14
// baseline (speedup 1.0000x reference)
#include <cuda_runtime.h>
#include <cuda_bf16.h>
#include <cstdint>

// Problem constants (fixed shapes for TrivialDecoder_1236950581455)
#define E_GROUPS 65536
#define KNEG     16
#define GROUP    17
#define PAIRS    (E_GROUPS * GROUP)   // 1,114,112
#define N_ROWS   1000000
#define D        64
#define KDIM     192
#define M_TILE   128
#define NTILE_TOT (PAIRS / M_TILE)    // 8704
#define THREADS  256                  // 8 warps, each owns 16 m-rows
#define KSTEPS   6                    // 192 / 32 (fp8 k32 mma)
#define NTILES   8                    // 64 / 8
#define GRID_SC  444                  // 148 SMs x 3 CTAs

#define APITCH   208                  // A: bytes per row (e4m3), conflict-free LDS

// SMEM byte layout: total 39936 B -> 3 CTAs/SM
#define SMEM_B1    0                          // 64 floats
#define SMEM_W2    256                        // 64 floats
#define SMEM_A     1024                       // 128 x 208 = 26624 B
#define SMEM_B     (1024 + 128 * APITCH)      // packed B: 1536 x 8 = 12288 B
#define SMEM_TOTAL (SMEM_B + 12288)           // 39936

__device__ float g_scores[PAIRS];
// e4m3 mirror of the embedding table: 64 MB -> fully L2-resident.
__device__ __align__(16) uint8_t g_emb8[(size_t)N_ROWS * 64];

__global__ void zero_out_kernel(float* out) { out[0] = 0.0f; }

// ---------------- portable PTX helpers ----------------
// cvt.e4m3x2: a -> high byte, b -> low byte. k-ascending in ascending bytes.
__device__ __forceinline__ uint32_t pack4_e4m3(float x0, float x1, float x2, float x3) {
    uint16_t lo, hi;
    asm("cvt.rn.satfinite.e4m3x2.f32 %0, %1, %2;" : "=h"(lo) : "f"(x1), "f"(x0));
    asm("cvt.rn.satfinite.e4m3x2.f32 %0, %1, %2;" : "=h"(hi) : "f"(x3), "f"(x2));
    return (uint32_t)lo | ((uint32_t)hi << 16);
}

// Elementwise product of 4 packed e4m3 bytes (decode->f16 mul->re-encode).
__device__ __forceinline__ uint32_t mul_e4m3x4(uint32_t u, uint32_t v) {
    uint16_t ul = (uint16_t)u, uh = (uint16_t)(u >> 16);
    uint16_t vl = (uint16_t)v, vh = (uint16_t)(v >> 16);
    uint32_t a, b, c, d, p0, p1;
    asm("cvt.rn.f16x2.e4m3x2 %0, %1;" : "=r"(a) : "h"(ul));
    asm("cvt.rn.f16x2.e4m3x2 %0, %1;" : "=r"(b) : "h"(uh));
    asm("cvt.rn.f16x2.e4m3x2 %0, %1;" : "=r"(c) : "h"(vl));
    asm("cvt.rn.f16x2.e4m3x2 %0, %1;" : "=r"(d) : "h"(vh));
    asm("mul.rn.f16x2 %0, %1, %2;" : "=r"(p0) : "r"(a), "r"(c));
    asm("mul.rn.f16x2 %0, %1, %2;" : "=r"(p1) : "r"(b), "r"(d));
    uint16_t rl, rh;
    asm("cvt.rn.satfinite.e4m3x2.f16x2 %0, %1;" : "=h"(rl) : "r"(p0));
    asm("cvt.rn.satfinite.e4m3x2.f16x2 %0, %1;" : "=h"(rh) : "r"(p1));
    return (uint32_t)rl | ((uint32_t)rh << 16);
}

__device__ __forceinline__ void mma_16832_e4m3(float* c, const uint32_t* a,
                                               uint32_t b0, uint32_t b1) {
    asm volatile(
        "mma.sync.aligned.m16n8k32.row.col.f32.e4m3.e4m3.f32 "
        "{%0,%1,%2,%3}, {%4,%5,%6,%7}, {%8,%9}, {%0,%1,%2,%3};"
        : "+f"(c[0]), "+f"(c[1]), "+f"(c[2]), "+f"(c[3])
        : "r"(a[0]), "r"(a[1]), "r"(a[2]), "r"(a[3]), "r"(b0), "r"(b1));
}

// ---------------------------------------------------------------------------
// Kernel 0: fp32 -> e4m3 table conversion (streaming, memory-bound).
// One thread per 16 floats.
// ---------------------------------------------------------------------------
__global__ void __launch_bounds__(256)
convert_table_kernel(const float* __restrict__ embeds)
{
    size_t i = (size_t)blockIdx.x * 256 + threadIdx.x;   // 4,000,000 threads
    const float4* src = (const float4*)embeds + i * 4;
    float4 a = src[0], b = src[1], c = src[2], d = src[3];
    uint4 v = make_uint4(pack4_e4m3(a.x, a.y, a.z, a.w),
                         pack4_e4m3(b.x, b.y, b.z, b.w),
                         pack4_e4m3(c.x, c.y, c.z, c.w),
                         pack4_e4m3(d.x, d.y, d.z, d.w));
    *(uint4*)(g_emb8 + i * 16) = v;
}

// ---------------------------------------------------------------------------
// Kernel 1: persistent, barrier-free warp pipelines; 8 warps x 16 m-rows.
// Gather reads the e4m3 table (L2-resident): u/v copied raw, u*v via f16.
// B (W1) packed in shared (8B LDS per fragment). fp8 mma, fp32 accumulate.
// ---------------------------------------------------------------------------
__global__ void __launch_bounds__(THREADS, 3)
score_kernel(const int*   __restrict__ pos,
             const int*   __restrict__ neg,
             const float* __restrict__ W1,
             const float* __restrict__ b1,
             const float* __restrict__ W2,
             const float* __restrict__ b2)
{
    extern __shared__ char smem[];
    const int tid = threadIdx.x;
    const int wid = tid >> 5;
    const int lid = tid & 31;
    const int g   = lid >> 2;          // fragment row/col group
    const int tg  = lid & 3;           // thread-in-group

    // One-time staging: b1, W2 to shared.
    if (tid < 64) {
        ((float*)(smem + SMEM_B1))[tid] = b1[tid];
        ((float*)(smem + SMEM_W2))[tid] = W2[tid];
    }
    // Stage W1 as PACKED e4m3 fragment entries (scaled x8).
    for (int c = tid; c < 64 * 24; c += THREADS) {
        int n   = c / 24;
        int rem = c - n * 24;
        int ks  = rem >> 2;
        int tt  = rem & 3;
        int nt  = n >> 3;
        int gg  = n & 7;
        const float4* wp0 = (const float4*)(W1 + n * KDIM + ks * 32 + tt * 4);
        const float4* wp1 = (const float4*)(W1 + n * KDIM + ks * 32 + 16 + tt * 4);
        float4 w0 = *wp0, w1 = *wp1;
        uint2 v = make_uint2(
            pack4_e4m3(w0.x * 8.0f, w0.y * 8.0f, w0.z * 8.0f, w0.w * 8.0f),
            pack4_e4m3(w1.x * 8.0f, w1.y * 8.0f, w1.z * 8.0f, w1.w * 8.0f));
        int e = ((nt * 6 + ks) * 8 + gg) * 4 + tt;
        *(uint2*)(smem + SMEM_B + e * 8) = v;
    }
    __syncthreads();   // only block barrier in the kernel

    const float b2v = b2[0];
    const int j = lid & 3;             // 16B chunk within the 64B row

    for (int t = blockIdx.x; t < NTILE_TOT; t += GRID_SC) {
        const int p0 = t * M_TILE;

        // ---- gather: warp owns rows [16*wid, 16*wid+16); 4 lanes per row ----
        int iu_r = 0, iv_r = 0;
        if (lid < 16) {
            int p = p0 + wid * 16 + lid;
            unsigned e = (unsigned)p / 17u;
            unsigned jj = (unsigned)p - e * 17u;
            const int* pr = (jj == 0) ? (pos + 2 * e)
                                      : (neg + 2 * (e * KNEG + (jj - 1)));
            iu_r = pr[0];
            iv_r = pr[1];
        }
        // Batch both iterations' loads (4 LDG.128 in flight), then store.
        int r0 = (lid >> 2), r1 = 8 + (lid >> 2);
        int iu0 = __shfl_sync(0xffffffffu, iu_r, r0);
        int iv0 = __shfl_sync(0xffffffffu, iv_r, r0);
        int iu1 = __shfl_sync(0xffffffffu, iu_r, r1);
        int iv1 = __shfl_sync(0xffffffffu, iv_r, r1);
        uint4 u0 = *(const uint4*)(g_emb8 + (size_t)iu0 * 64 + j * 16);
        uint4 v0 = *(const uint4*)(g_emb8 + (size_t)iv0 * 64 + j * 16);
        uint4 u1 = *(const uint4*)(g_emb8 + (size_t)iu1 * 64 + j * 16);
        uint4 v1 = *(const uint4*)(g_emb8 + (size_t)iv1 * 64 + j * 16);
        {
            char* xr = smem + SMEM_A + (wid * 16 + r0) * APITCH;
            *(uint4*)(xr + j * 16)       = u0;
            *(uint4*)(xr + 64 + j * 16)  = v0;
            *(uint4*)(xr + 128 + j * 16) = make_uint4(
                mul_e4m3x4(u0.x, v0.x), mul_e4m3x4(u0.y, v0.y),
                mul_e4m3x4(u0.z, v0.z), mul_e4m3x4(u0.w, v0.w));
        }
        {
            char* xr = smem + SMEM_A + (wid * 16 + r1) * APITCH;
            *(uint4*)(xr + j * 16)       = u1;
            *(uint4*)(xr + 64 + j * 16)  = v1;
            *(uint4*)(xr + 128 + j * 16) = make_uint4(
                mul_e4m3x4(u1.x, v1.x), mul_e4m3x4(u1.y, v1.y),
                mul_e4m3x4(u1.z, v1.z), mul_e4m3x4(u1.w, v1.w));
        }
        __syncwarp();   // order gather STS before cross-lane fragment LDS

        // ---- GEMM: warp tile 16(m) x 64(n), K=192; B via packed 8B LDS ----
        float c0[NTILES][4];
        #pragma unroll
        for (int nt = 0; nt < NTILES; nt++) {
            c0[nt][0] = c0[nt][1] = c0[nt][2] = c0[nt][3] = 0.0f;
        }
        #pragma unroll
        for (int ks = 0; ks < KSTEPS; ks++) {
            uint32_t a0[4];
            {
                const char* ar = smem + SMEM_A + (wid * 16 + g) * APITCH + ks * 32 + tg * 4;
                a0[0] = *(const uint32_t*)(ar);
                a0[1] = *(const uint32_t*)(ar + 8 * APITCH);
                a0[2] = *(const uint32_t*)(ar + 16);
                a0[3] = *(const uint32_t*)(ar + 8 * APITCH + 16);
            }
            #pragma unroll
            for (int nt = 0; nt < NTILES; nt++) {
                uint2 b = *(const uint2*)(smem + SMEM_B
                                          + ((nt * 6 + ks) * 32 + lid) * 8);
                mma_16832_e4m3(c0[nt], a0, b.x, b.y);
            }
        }

        // ---- epilogue in fragment layout (x0.125 undoes the W1 x8 scale) ----
        const float* b1s = (const float*)(smem + SMEM_B1);
        const float* w2s = (const float*)(smem + SMEM_W2);
        float z0 = 0.0f, z1 = 0.0f;
        #pragma unroll
        for (int nt = 0; nt < NTILES; nt++) {
            int n0 = nt * 8 + 2 * tg;
            float bb0 = b1s[n0], bb1 = b1s[n0 + 1];
            float ww0 = w2s[n0], ww1 = w2s[n0 + 1];
            float h;
            h = fmaf(c0[nt][0], 0.125f, bb0); h = h > 0.0f ? h : 0.0f; z0 += h * ww0;
            h = fmaf(c0[nt][1], 0.125f, bb1); h = h > 0.0f ? h : 0.0f; z0 += h * ww1;
            h = fmaf(c0[nt][2], 0.125f, bb0); h = h > 0.0f ? h : 0.0f; z1 += h * ww0;
            h = fmaf(c0[nt][3], 0.125f, bb1); h = h > 0.0f ? h : 0.0f; z1 += h * ww1;
        }
        z0 += __shfl_xor_sync(0xffffffffu, z0, 1);
        z0 += __shfl_xor_sync(0xffffffffu, z0, 2);
        z1 += __shfl_xor_sync(0xffffffffu, z1, 1);
        z1 += __shfl_xor_sync(0xffffffffu, z1, 2);

        if (tg == 0) {
            int r = p0 + wid * 16 + g;
            float s0 = 1.0f / (1.0f + expf(-(z0 + b2v)));
            float s1 = 1.0f / (1.0f + expf(-(z1 + b2v)));
            g_scores[r]     = expf(s0);
            g_scores[r + 8] = expf(s1);
        }
    }
}

// ---------------------------------------------------------------------------
// Kernel 2: per-group ratio + global reduction.
// ---------------------------------------------------------------------------
__global__ void __launch_bounds__(256)
loss_kernel(float* __restrict__ out)
{
    int e = blockIdx.x * blockDim.x + threadIdx.x;
    float term = 0.0f;
    if (e < E_GROUPS) {
        const float* s = g_scores + (long long)e * GROUP;
        float ps = s[0];
        float denom = ps;
        #pragma unroll
        for (int j = 1; j < GROUP; j++) denom += s[j];
        term = ps / (denom + 1e-8f) + 1e-8f;
    }
    #pragma unroll
    for (int o = 16; o; o >>= 1) term += __shfl_xor_sync(0xffffffffu, term, o);

    __shared__ float wsum[8];
    int l = threadIdx.x & 31;
    int w = threadIdx.x >> 5;
    if (l == 0) wsum[w] = term;
    __syncthreads();
    if (threadIdx.x < 8) {
        float t = wsum[threadIdx.x];
        #pragma unroll
        for (int o = 4; o; o >>= 1) t += __shfl_xor_sync(0x000000ffu, t, o);
        if (threadIdx.x == 0) atomicAdd(out, -t);
    }
}

extern "C" void kernel_launch(void* const* d_in, const int* in_sizes, int n_in,
                              void* d_out, int out_size)
{
    const float* embeds = (const float*)d_in[0];
    const int*   pos    = (const int*)  d_in[1];
    const int*   neg    = (const int*)  d_in[2];
    const float* W1     = (const float*)d_in[3];
    const float* b1     = (const float*)d_in[4];
    const float* W2     = (const float*)d_in[5];
    const float* b2     = (const float*)d_in[6];
    float*       out    = (float*)d_out;

    cudaFuncSetAttribute(score_kernel, cudaFuncAttributeMaxDynamicSharedMemorySize,
                         SMEM_TOTAL);

    // 64e6 floats / 16 per thread = 4,000,000 threads.
    convert_table_kernel<<<(N_ROWS * 64 / 16) / 256, 256>>>(embeds);
    score_kernel<<<GRID_SC, THREADS, SMEM_TOTAL>>>(pos, neg, W1, b1, W2, b2);
    zero_out_kernel<<<1, 1>>>(out);
    loss_kernel<<<E_GROUPS / 256, 256>>>(out);
}